// round 1
// baseline (speedup 1.0000x reference)
#include <cuda_runtime.h>
#include <stdint.h>
#include <math.h>

#define NB    16384
#define NPRE  1024
#define NPOST 512
#define BATCH 2
#define EPSI  1e-8f
#define THR   0.8f

// ---- scratch (no allocation allowed) ----
__device__ unsigned long long g_keys[BATCH * NB];
__device__ int                g_topidx[BATCH * NPRE];
__device__ float              g_bev[BATCH * NPRE * 5];
__device__ unsigned int       g_ovl[BATCH * NPRE * 32];   // bit j of row i: iou(i,j)>0.8, j>i

// ---------------------------------------------------------------------------
// Kernel 1: per-box score = max over 3 classes; pack sort key; zero ovl matrix
// key = (~monotone(scorebits) << 32) | box_index  -> ascending u64 sort gives
// descending score, ties broken by smaller index (matches lax.top_k).
// ---------------------------------------------------------------------------
__global__ void k_score(const float* __restrict__ cls) {
    int t = blockIdx.x * blockDim.x + threadIdx.x;
    if (t < BATCH * NB) {
        float a = cls[t * 3 + 0];
        float b = cls[t * 3 + 1];
        float c = cls[t * 3 + 2];
        float s = fmaxf(a, fmaxf(b, c));
        unsigned u = __float_as_uint(s);
        unsigned asc = (u & 0x80000000u) ? ~u : (u | 0x80000000u);
        unsigned desc = ~asc;
        g_keys[t] = (((unsigned long long)desc) << 32) | (unsigned)(t & (NB - 1));
        // zero overlap matrix (65536 words total, 32768 threads -> 2 each)
        g_ovl[t] = 0u;
        g_ovl[t + BATCH * NB] = 0u;
    }
}

// ---------------------------------------------------------------------------
// Kernel 2: full bitonic sort of 16384 u64 keys per batch (one block each),
// then emit top-1024 indices and their 5-dof BEV boxes (x,y,dx,dy,ry).
// ---------------------------------------------------------------------------
__global__ void __launch_bounds__(1024) k_sort(const float* __restrict__ box) {
    extern __shared__ unsigned long long sh[];
    int b = blockIdx.x;
    int tid = threadIdx.x;

    for (int i = tid; i < NB; i += blockDim.x) sh[i] = g_keys[b * NB + i];
    __syncthreads();

    for (int k = 2; k <= NB; k <<= 1) {
        for (int j = k >> 1; j > 0; j >>= 1) {
            for (int i = tid; i < NB; i += blockDim.x) {
                int ixj = i ^ j;
                if (ixj > i) {
                    unsigned long long x = sh[i], y = sh[ixj];
                    bool up = ((i & k) == 0);
                    if ((x > y) == up) { sh[i] = y; sh[ixj] = x; }
                }
            }
            __syncthreads();
        }
    }

    for (int r = tid; r < NPRE; r += blockDim.x) {
        int idx = (int)(sh[r] & 0xffffffffu);
        g_topidx[b * NPRE + r] = idx;
        const float* bp = box + ((size_t)b * NB + idx) * 7;
        float* o = g_bev + (b * NPRE + r) * 5;
        o[0] = bp[0];  // x
        o[1] = bp[1];  // y
        o[2] = bp[3];  // dx
        o[3] = bp[4];  // dy
        o[4] = bp[6];  // ry
    }
}

// ---------------------------------------------------------------------------
// Kernel 3: pairwise rotated-BEV IoU > 0.8 -> bitmask. Quick rejects first,
// then an exact replica of the reference polygon algorithm for survivors.
// ---------------------------------------------------------------------------
__global__ void __launch_bounds__(128) k_iou() {
    int t = blockIdx.x * 128 + threadIdx.x;
    int b = blockIdx.y;
    int i = t >> 10;
    int j = t & (NPRE - 1);
    if (i >= NPRE || j <= i) return;

    const float* A  = g_bev + (b * NPRE + i) * 5;
    const float* Bv = g_bev + (b * NPRE + j) * 5;
    float ax0 = A[0],  ay0 = A[1],  adx = A[2],  ady = A[3],  ar = A[4];
    float bx0 = Bv[0], by0 = Bv[1], bdx = Bv[2], bdy = Bv[3], br = Bv[4];

    // reject 1: circles can't overlap -> inter = 0 -> iou = 0
    float ddx = bx0 - ax0, ddy = by0 - ay0;
    float ra = 0.5f * sqrtf(adx * adx + ady * ady);
    float rb = 0.5f * sqrtf(bdx * bdx + bdy * bdy);
    float rr = ra + rb;
    if (ddx * ddx + ddy * ddy > rr * rr) return;

    // reject 2: iou <= min(Aa,Ab)/max(Aa,Ab); if that bound <= 0.79 => iou < 0.8
    float Aa = adx * ady, Ab = bdx * bdy;
    float mn = fminf(Aa, Ab), mx = fmaxf(Aa, Ab);
    if (mn <= 0.79f * mx) return;

    // ---- full reference algorithm ----
    float acr = cosf(ar), asr = sinf(ar);
    float bcr = cosf(br), bsr = sinf(br);
    const float offx[4] = { 0.5f, -0.5f, -0.5f,  0.5f };
    const float offy[4] = { 0.5f,  0.5f, -0.5f, -0.5f };

    float ax[4], ay[4], bx[4], by[4];
#pragma unroll
    for (int k = 0; k < 4; k++) {
        float lx = adx * offx[k], ly = ady * offy[k];
        ax[k] = ax0 + lx * acr - ly * asr;
        ay[k] = ay0 + lx * asr + ly * acr;
        lx = bdx * offx[k]; ly = bdy * offy[k];
        bx[k] = bx0 + lx * bcr - ly * bsr;
        by[k] = by0 + lx * bsr + ly * bcr;
    }
    float dax[4], day[4], dbx[4], dby[4];
#pragma unroll
    for (int k = 0; k < 4; k++) {
        dax[k] = ax[(k + 1) & 3] - ax[k];
        day[k] = ay[(k + 1) & 3] - ay[k];
        dbx[k] = bx[(k + 1) & 3] - bx[k];
        dby[k] = by[(k + 1) & 3] - by[k];
    }

    float px[24], py[24];
    bool  mk[24];
    // 16 edge-edge intersection candidates (A-edge-major order, matches reshape)
#pragma unroll
    for (int ia = 0; ia < 4; ia++) {
#pragma unroll
        for (int jb = 0; jb < 4; jb++) {
            int id = ia * 4 + jb;
            float den = dax[ia] * dby[jb] - day[ia] * dbx[jb];
            float dx = bx[jb] - ax[ia], dy = by[jb] - ay[ia];
            float dens = (fabsf(den) > EPSI) ? den : 1.0f;
            float tt = (dx * dby[jb] - dy * dbx[jb]) / dens;
            float uu = (dx * day[ia] - dy * dax[ia]) / dens;
            mk[id] = (fabsf(den) > EPSI) && tt >= 0.0f && tt <= 1.0f &&
                     uu >= 0.0f && uu <= 1.0f;
            px[id] = ax[ia] + tt * dax[ia];
            py[id] = ay[ia] + tt * day[ia];
        }
    }
    // corners of A in B (16..19), corners of B in A (20..23)
#pragma unroll
    for (int k = 0; k < 4; k++) {
        float rx = ax[k] - bx0, ry = ay[k] - by0;
        float qx = rx * bcr + ry * bsr;
        float qy = -rx * bsr + ry * bcr;
        mk[16 + k] = (fabsf(qx) <= bdx * 0.5f + 1e-5f) &&
                     (fabsf(qy) <= bdy * 0.5f + 1e-5f);
        px[16 + k] = ax[k]; py[16 + k] = ay[k];

        rx = bx[k] - ax0; ry = by[k] - ay0;
        qx = rx * acr + ry * asr;
        qy = -rx * asr + ry * acr;
        mk[20 + k] = (fabsf(qx) <= adx * 0.5f + 1e-5f) &&
                     (fabsf(qy) <= ady * 0.5f + 1e-5f);
        px[20 + k] = bx[k]; py[20 + k] = by[k];
    }

    // masked centroid
    int cnt = 0;
    float sx = 0.0f, sy = 0.0f;
#pragma unroll
    for (int k = 0; k < 24; k++) {
        if (mk[k]) { cnt++; sx += px[k]; sy += py[k]; }
    }
    float fc = (float)(cnt > 0 ? cnt : 1);
    float ctx = sx / fc, cty = sy / fc;

    // angles (masked -> 1e9), stable insertion argsort ascending
    float ang[24];
#pragma unroll
    for (int k = 0; k < 24; k++)
        ang[k] = mk[k] ? atan2f(py[k] - cty, px[k] - ctx) : 1e9f;

    int ord[24];
#pragma unroll
    for (int k = 0; k < 24; k++) ord[k] = k;
    for (int a2 = 1; a2 < 24; a2++) {
        int o = ord[a2];
        float key = ang[o];
        int c = a2 - 1;
        while (c >= 0 && ang[ord[c]] > key) { ord[c + 1] = ord[c]; c--; }
        ord[c + 1] = o;
    }

    // poly = where(msk_sorted, pts_sorted, first); shoelace over 24 verts
    float fxp = px[ord[0]], fyp = py[ord[0]];
    float s2 = 0.0f;
#pragma unroll
    for (int k = 0; k < 24; k++) {
        int o  = ord[k];
        int o2 = ord[(k + 1) % 24];
        float x0 = mk[o]  ? px[o]  : fxp;
        float y0 = mk[o]  ? py[o]  : fyp;
        float x1 = mk[o2] ? px[o2] : fxp;
        float y1 = mk[o2] ? py[o2] : fyp;
        s2 += x0 * y1 - y0 * x1;
    }
    float inter = 0.5f * fabsf(s2);
    float iou = inter / fmaxf(Aa + Ab - inter, 1e-6f);

    if (iou > THR)
        atomicOr(&g_ovl[(b * NPRE + i) * 32 + (j >> 5)], 1u << (j & 31));
}

// ---------------------------------------------------------------------------
// Kernel 4: greedy NMS (1 warp, sequential over 1024 rows), kept-list build,
// and final output gather: rois | scores | labels(+1) | logits  (all f32)
// ---------------------------------------------------------------------------
__global__ void __launch_bounds__(512) k_nms(const float* __restrict__ box,
                                             const float* __restrict__ cls,
                                             float* __restrict__ out) {
    int b = blockIdx.x;
    int tid = threadIdx.x;

    __shared__ unsigned int supp[32];
    __shared__ int list[NPOST];
    __shared__ int cnt;

    if (tid < 32) supp[tid] = 0u;
    __syncthreads();

    if (tid < 32) {
        const unsigned int* rows = g_ovl + b * NPRE * 32;
        for (int i = 0; i < NPRE; i++) {
            bool sup = (supp[i >> 5] >> (i & 31)) & 1u;
            __syncwarp();
            if (!sup) supp[tid] |= rows[i * 32 + tid];
            __syncwarp();
        }
    }
    __syncthreads();

    if (tid == 0) {
        int c = 0;
        for (int i = 0; i < NPRE && c < NPOST; i++)
            if (!((supp[i >> 5] >> (i & 31)) & 1u)) list[c++] = i;
        cnt = c;
    }
    __syncthreads();

    if (tid < NPOST) {
        float* rois   = out;
        float* scores = out + BATCH * NPOST * 7;
        float* labels = scores + BATCH * NPOST;
        float* logits = labels + BATCH * NPOST;
        int row = b * NPOST + tid;

        if (tid < cnt) {
            int pos = list[tid];
            int sel = g_topidx[b * NPRE + pos];
            const float* bp = box + ((size_t)b * NB + sel) * 7;
            const float* lp = cls + ((size_t)b * NB + sel) * 3;
#pragma unroll
            for (int k = 0; k < 7; k++) rois[row * 7 + k] = bp[k];
            float l0 = lp[0], l1 = lp[1], l2 = lp[2];
            logits[row * 3 + 0] = l0;
            logits[row * 3 + 1] = l1;
            logits[row * 3 + 2] = l2;
            float best = l0; int lab = 0;
            if (l1 > best) { best = l1; lab = 1; }
            if (l2 > best) { best = l2; lab = 2; }
            scores[row] = best;
            labels[row] = (float)(lab + 1);
        } else {
#pragma unroll
            for (int k = 0; k < 7; k++) rois[row * 7 + k] = 0.0f;
            logits[row * 3 + 0] = 0.0f;
            logits[row * 3 + 1] = 0.0f;
            logits[row * 3 + 2] = 0.0f;
            scores[row] = 0.0f;
            labels[row] = 1.0f;   // where(valid, labels, 0) + 1
        }
    }
}

// ---------------------------------------------------------------------------
extern "C" void kernel_launch(void* const* d_in, const int* in_sizes, int n_in,
                              void* d_out, int out_size) {
    const float* box = (const float*)d_in[0];  // (2,16384,7)
    const float* cls = (const float*)d_in[1];  // (2,16384,3)
    float* out = (float*)d_out;

    cudaFuncSetAttribute(k_sort, cudaFuncAttributeMaxDynamicSharedMemorySize,
                         NB * (int)sizeof(unsigned long long));

    k_score<<<(BATCH * NB + 255) / 256, 256>>>(cls);
    k_sort<<<BATCH, 1024, NB * sizeof(unsigned long long)>>>(box);
    dim3 g((NPRE * NPRE + 127) / 128, BATCH);
    k_iou<<<g, 128>>>();
    k_nms<<<BATCH, 512>>>(box, cls, out);
}

// round 3
// speedup vs baseline: 5.3461x; 5.3461x over previous
#include <cuda_runtime.h>
#include <stdint.h>
#include <math.h>

#define NB    16384
#define NPRE  1024
#define NPOST 512
#define BATCH 2
#define EPSI  1e-8f
#define THR   0.8f
#define NCAND 4096
#define NBINS 16384

// ---- scratch (no device allocation allowed) ----
__device__ int          g_topidx[BATCH * NPRE];
__device__ float        g_bev[BATCH * NPRE * 5];
__device__ unsigned int g_ovl[BATCH * NPRE * 32]; // bit j of row i: iou(i,j)>0.8, j>i

// monotone descending transform: higher score -> smaller u32
__device__ __forceinline__ unsigned desc_bits(float s) {
    unsigned u = __float_as_uint(s);
    unsigned asc = (u & 0x80000000u) ? ~u : (u | 0x80000000u);
    return ~asc;
}

// ---------------------------------------------------------------------------
// Kernel 1: exact top-1024 select + sort via 14-bit histogram radix-select.
// One block per batch, 1024 threads. Also zeroes this batch's g_ovl.
// smem: hist[16384] u32 (64KB) + cand[4096] u64 (32KB) = 96KB dynamic.
// ---------------------------------------------------------------------------
__global__ void __launch_bounds__(1024) k_select(const float* __restrict__ box,
                                                 const float* __restrict__ cls) {
    extern __shared__ unsigned char smem_raw[];
    unsigned int*       hist = (unsigned int*)smem_raw;
    unsigned long long* cand = (unsigned long long*)(smem_raw + NBINS * 4);

    __shared__ unsigned int warpsum[32];
    __shared__ int bstar;
    __shared__ int cnt;

    int b   = blockIdx.x;
    int tid = threadIdx.x;
    int lane = tid & 31, wid = tid >> 5;

    // zero histogram + overlap matrix
    #pragma unroll
    for (int k = 0; k < NBINS / 1024; k++) hist[tid + k * 1024] = 0u;
    unsigned int* ovl = g_ovl + b * NPRE * 32;
    #pragma unroll
    for (int k = 0; k < NPRE * 32 / 1024; k++) ovl[tid + k * 1024] = 0u;
    if (tid == 0) cnt = 0;
    __syncthreads();

    // pass 1: histogram of top-14 key bits
    const float* cb = cls + (size_t)b * NB * 3;
    #pragma unroll
    for (int k = 0; k < NB / 1024; k++) {
        int t = tid + k * 1024;
        float s = fmaxf(cb[t * 3 + 0], fmaxf(cb[t * 3 + 1], cb[t * 3 + 2]));
        atomicAdd(&hist[desc_bits(s) >> 18], 1u);
    }
    __syncthreads();

    // prefix-scan to locate b* = first bin with inclusive cumulative >= 1024
    unsigned s16 = 0;
    #pragma unroll
    for (int k = 0; k < 16; k++) s16 += hist[tid * 16 + k];
    unsigned p = s16;
    #pragma unroll
    for (int off = 1; off < 32; off <<= 1) {
        unsigned v = __shfl_up_sync(0xffffffffu, p, off);
        if (lane >= off) p += v;
    }
    if (lane == 31) warpsum[wid] = p;
    __syncthreads();
    if (tid < 32) {
        unsigned q = warpsum[tid];
        #pragma unroll
        for (int off = 1; off < 32; off <<= 1) {
            unsigned v = __shfl_up_sync(0xffffffffu, q, off);
            if (tid >= off) q += v;
        }
        warpsum[tid] = q;
    }
    __syncthreads();
    unsigned basePre = (wid > 0 ? warpsum[wid - 1] : 0u) + p - s16;
    if (basePre < NPRE && basePre + s16 >= NPRE) {
        unsigned run = basePre;
        #pragma unroll
        for (int k = 0; k < 16; k++) {
            unsigned c = hist[tid * 16 + k];
            if (run < NPRE && run + c >= NPRE) { bstar = tid * 16 + k; break; }
            run += c;
        }
    }
    __syncthreads();
    int bs = bstar;

    // pass 2: compact candidates (bin <= b*)
    #pragma unroll
    for (int k = 0; k < NB / 1024; k++) {
        int t = tid + k * 1024;
        float s = fmaxf(cb[t * 3 + 0], fmaxf(cb[t * 3 + 1], cb[t * 3 + 2]));
        unsigned d = desc_bits(s);
        if ((int)(d >> 18) <= bs) {
            int pos = atomicAdd(&cnt, 1);
            if (pos < NCAND)
                cand[pos] = (((unsigned long long)d) << 32) | (unsigned)t;
        }
    }
    __syncthreads();
    int c0 = cnt;
    for (int i = tid; i < NCAND; i += 1024)
        if (i >= c0) cand[i] = 0xffffffffffffffffull;
    __syncthreads();

    // bitonic sort 4096 candidates (ascending = best first)
    for (int k = 2; k <= NCAND; k <<= 1) {
        for (int j = k >> 1; j > 0; j >>= 1) {
            #pragma unroll
            for (int q = 0; q < NCAND / 1024; q++) {
                int i = tid + q * 1024;
                int ixj = i ^ j;
                if (ixj > i) {
                    unsigned long long x = cand[i], y = cand[ixj];
                    bool up = ((i & k) == 0);
                    if ((x > y) == up) { cand[i] = y; cand[ixj] = x; }
                }
            }
            __syncthreads();
        }
    }

    // emit top-1024: indices + BEV boxes
    {
        int idx = (int)(cand[tid] & 0xffffffffu);
        g_topidx[b * NPRE + tid] = idx;
        const float* bp = box + ((size_t)b * NB + idx) * 7;
        float* o = g_bev + (b * NPRE + tid) * 5;
        o[0] = bp[0]; o[1] = bp[1]; o[2] = bp[3]; o[3] = bp[4]; o[4] = bp[6];
    }
}

// ---------------------------------------------------------------------------
// Kernel 2: pairwise rotated-BEV IoU > 0.8 -> bitmask. Quick rejects first,
// then an exact replica of the reference polygon algorithm for survivors.
// ---------------------------------------------------------------------------
__global__ void __launch_bounds__(128) k_iou() {
    int t = blockIdx.x * 128 + threadIdx.x;
    int b = blockIdx.y;
    int i = t >> 10;
    int j = t & (NPRE - 1);
    if (j <= i) return;

    const float* A  = g_bev + (b * NPRE + i) * 5;
    const float* Bv = g_bev + (b * NPRE + j) * 5;
    float ax0 = A[0],  ay0 = A[1],  adx = A[2],  ady = A[3],  ar = A[4];
    float bx0 = Bv[0], by0 = Bv[1], bdx = Bv[2], bdy = Bv[3], br = Bv[4];

    // reject 1: enclosing circles disjoint -> inter = 0
    float ddx = bx0 - ax0, ddy = by0 - ay0;
    float ra = 0.5f * sqrtf(adx * adx + ady * ady);
    float rb = 0.5f * sqrtf(bdx * bdx + bdy * bdy);
    float rr = ra + rb;
    if (ddx * ddx + ddy * ddy > rr * rr) return;

    // reject 2: iou <= min(area)/max(area)
    float Aa = adx * ady, Ab = bdx * bdy;
    float mn = fminf(Aa, Ab), mx = fmaxf(Aa, Ab);
    if (mn <= 0.79f * mx) return;

    // ---- full reference algorithm ----
    float acr = cosf(ar), asr = sinf(ar);
    float bcr = cosf(br), bsr = sinf(br);
    const float offx[4] = { 0.5f, -0.5f, -0.5f,  0.5f };
    const float offy[4] = { 0.5f,  0.5f, -0.5f, -0.5f };

    float ax[4], ay[4], bx[4], by[4];
#pragma unroll
    for (int k = 0; k < 4; k++) {
        float lx = adx * offx[k], ly = ady * offy[k];
        ax[k] = ax0 + lx * acr - ly * asr;
        ay[k] = ay0 + lx * asr + ly * acr;
        lx = bdx * offx[k]; ly = bdy * offy[k];
        bx[k] = bx0 + lx * bcr - ly * bsr;
        by[k] = by0 + lx * bsr + ly * bcr;
    }
    float dax[4], day[4], dbx[4], dby[4];
#pragma unroll
    for (int k = 0; k < 4; k++) {
        dax[k] = ax[(k + 1) & 3] - ax[k];
        day[k] = ay[(k + 1) & 3] - ay[k];
        dbx[k] = bx[(k + 1) & 3] - bx[k];
        dby[k] = by[(k + 1) & 3] - by[k];
    }

    float px[24], py[24];
    bool  mk[24];
#pragma unroll
    for (int ia = 0; ia < 4; ia++) {
#pragma unroll
        for (int jb = 0; jb < 4; jb++) {
            int id = ia * 4 + jb;
            float den = dax[ia] * dby[jb] - day[ia] * dbx[jb];
            float dx = bx[jb] - ax[ia], dy = by[jb] - ay[ia];
            float dens = (fabsf(den) > EPSI) ? den : 1.0f;
            float tt = (dx * dby[jb] - dy * dbx[jb]) / dens;
            float uu = (dx * day[ia] - dy * dax[ia]) / dens;
            mk[id] = (fabsf(den) > EPSI) && tt >= 0.0f && tt <= 1.0f &&
                     uu >= 0.0f && uu <= 1.0f;
            px[id] = ax[ia] + tt * dax[ia];
            py[id] = ay[ia] + tt * day[ia];
        }
    }
#pragma unroll
    for (int k = 0; k < 4; k++) {
        float rx = ax[k] - bx0, ry = ay[k] - by0;
        float qx = rx * bcr + ry * bsr;
        float qy = -rx * bsr + ry * bcr;
        mk[16 + k] = (fabsf(qx) <= bdx * 0.5f + 1e-5f) &&
                     (fabsf(qy) <= bdy * 0.5f + 1e-5f);
        px[16 + k] = ax[k]; py[16 + k] = ay[k];

        rx = bx[k] - ax0; ry = by[k] - ay0;
        qx = rx * acr + ry * asr;
        qy = -rx * asr + ry * acr;
        mk[20 + k] = (fabsf(qx) <= adx * 0.5f + 1e-5f) &&
                     (fabsf(qy) <= ady * 0.5f + 1e-5f);
        px[20 + k] = bx[k]; py[20 + k] = by[k];
    }

    int cntm = 0;
    float sx = 0.0f, sy = 0.0f;
#pragma unroll
    for (int k = 0; k < 24; k++)
        if (mk[k]) { cntm++; sx += px[k]; sy += py[k]; }
    float fc = (float)(cntm > 0 ? cntm : 1);
    float ctx = sx / fc, cty = sy / fc;

    float ang[24];
#pragma unroll
    for (int k = 0; k < 24; k++)
        ang[k] = mk[k] ? atan2f(py[k] - cty, px[k] - ctx) : 1e9f;

    int ord[24];
#pragma unroll
    for (int k = 0; k < 24; k++) ord[k] = k;
    for (int a2 = 1; a2 < 24; a2++) {
        int o = ord[a2];
        float key = ang[o];
        int c = a2 - 1;
        while (c >= 0 && ang[ord[c]] > key) { ord[c + 1] = ord[c]; c--; }
        ord[c + 1] = o;
    }

    float fxp = px[ord[0]], fyp = py[ord[0]];
    float s2 = 0.0f;
#pragma unroll
    for (int k = 0; k < 24; k++) {
        int o  = ord[k];
        int o2 = ord[(k + 1) % 24];
        float x0 = mk[o]  ? px[o]  : fxp;
        float y0 = mk[o]  ? py[o]  : fyp;
        float x1 = mk[o2] ? px[o2] : fxp;
        float y1 = mk[o2] ? py[o2] : fyp;
        s2 += x0 * y1 - y0 * x1;
    }
    float inter = 0.5f * fabsf(s2);
    float iou = inter / fmaxf(Aa + Ab - inter, 1e-6f);

    if (iou > THR)
        atomicOr(&g_ovl[(b * NPRE + i) * 32 + (j >> 5)], 1u << (j & 31));
}

// ---------------------------------------------------------------------------
// Kernel 3: greedy NMS over nonzero rows only (matrix staged in smem),
// keep-list build (warp scan), and final output gather.
// Dynamic smem: 128KB row cache.
// ---------------------------------------------------------------------------
__global__ void __launch_bounds__(1024) k_nms(const float* __restrict__ box,
                                              const float* __restrict__ cls,
                                              float* __restrict__ out) {
    extern __shared__ unsigned int rowsSh[];   // NPRE*32 = 32768 words
    __shared__ unsigned int nzw[32];
    __shared__ unsigned int supp[32];
    __shared__ int listArr[NPOST];
    __shared__ int keepTotSh;

    int b = blockIdx.x;
    int tid = threadIdx.x;

    if (tid < 32) nzw[tid] = 0u;
    __syncthreads();

    // coalesced copy + nonzero-row bitmap (atomics only on nonzero words)
    const unsigned int* base = g_ovl + b * NPRE * 32;
    #pragma unroll
    for (int k = 0; k < NPRE * 32 / 1024; k++) {
        int idx = tid + k * 1024;
        unsigned v = base[idx];
        rowsSh[idx] = v;
        if (v) {
            int row = idx >> 5;
            atomicOr(&nzw[row >> 5], 1u << (row & 31));
        }
    }
    __syncthreads();

    if (tid < 32) {
        unsigned supw = 0u;
        for (int w = 0; w < 32; w++) {
            unsigned m = nzw[w];
            while (m) {
                int bit = __ffs(m) - 1; m &= m - 1;
                int i = w * 32 + bit;
                unsigned sw = __shfl_sync(0xffffffffu, supw, i >> 5);
                if (!((sw >> (i & 31)) & 1u))
                    supw |= rowsSh[i * 32 + tid];
            }
        }
        supp[tid] = supw;

        // build ordered keep list (first NPOST kept rows)
        unsigned kw = ~supw;
        int c = __popc(kw);
        int pre = c;
        #pragma unroll
        for (int off = 1; off < 32; off <<= 1) {
            int v = __shfl_up_sync(0xffffffffu, pre, off);
            if (tid >= off) pre += v;
        }
        int excl = pre - c;
        if (tid == 31) keepTotSh = pre;
        unsigned mm = kw;
        int o = excl;
        while (mm && o < NPOST) {
            int bit = __ffs(mm) - 1; mm &= mm - 1;
            listArr[o++] = tid * 32 + bit;
        }
    }
    __syncthreads();

    int keepTot = keepTotSh;
    if (keepTot > NPOST) keepTot = NPOST;

    if (tid < NPOST) {
        float* rois   = out;
        float* scores = out + BATCH * NPOST * 7;
        float* labels = scores + BATCH * NPOST;
        float* logits = labels + BATCH * NPOST;
        int row = b * NPOST + tid;

        if (tid < keepTot) {
            int pos = listArr[tid];
            int sel = g_topidx[b * NPRE + pos];
            const float* bp = box + ((size_t)b * NB + sel) * 7;
            const float* lp = cls + ((size_t)b * NB + sel) * 3;
            #pragma unroll
            for (int k = 0; k < 7; k++) rois[row * 7 + k] = bp[k];
            float l0 = lp[0], l1 = lp[1], l2 = lp[2];
            logits[row * 3 + 0] = l0;
            logits[row * 3 + 1] = l1;
            logits[row * 3 + 2] = l2;
            float best = l0; int lab = 0;
            if (l1 > best) { best = l1; lab = 1; }
            if (l2 > best) { best = l2; lab = 2; }
            scores[row] = best;
            labels[row] = (float)(lab + 1);
        } else {
            #pragma unroll
            for (int k = 0; k < 7; k++) rois[row * 7 + k] = 0.0f;
            logits[row * 3 + 0] = 0.0f;
            logits[row * 3 + 1] = 0.0f;
            logits[row * 3 + 2] = 0.0f;
            scores[row] = 0.0f;
            labels[row] = 1.0f;
        }
    }
}

// ---------------------------------------------------------------------------
extern "C" void kernel_launch(void* const* d_in, const int* in_sizes, int n_in,
                              void* d_out, int out_size) {
    const float* box = (const float*)d_in[0];  // (2,16384,7)
    const float* cls = (const float*)d_in[1];  // (2,16384,3)
    float* out = (float*)d_out;

    static bool attr_set = false;
    if (!attr_set) {
        cudaFuncSetAttribute(k_select, cudaFuncAttributeMaxDynamicSharedMemorySize,
                             NBINS * 4 + NCAND * 8);
        cudaFuncSetAttribute(k_nms, cudaFuncAttributeMaxDynamicSharedMemorySize,
                             NPRE * 32 * 4);
        attr_set = true;
    }

    k_select<<<BATCH, 1024, NBINS * 4 + NCAND * 8>>>(box, cls);
    dim3 g((NPRE * NPRE) / 128, BATCH);
    k_iou<<<g, 128>>>();
    k_nms<<<BATCH, 1024, NPRE * 32 * 4>>>(box, cls, out);
}